// round 6
// baseline (speedup 1.0000x reference)
#include <cuda_runtime.h>
#include <math.h>

// q,k,v : (B=16, C=512, L=1024) fp32
// score[b,i,j] = sum_c k[b,c,i]*q[b,c,j] / 32 ; w = softmax over BATCH axis ;
// out[b,c,j] = sum_i v[b,c,i]*w[b,i,j]

#define BATCH 16
#define CDIM  512
#define LDIM  1024

// 64 MB scratch for score / softmax weights (device global: allocation-free)
__device__ float g_score[(size_t)BATCH * LDIM * LDIM];

// ---------------- PTX helpers ----------------
__device__ __forceinline__ unsigned f2tf32(unsigned xbits) {
    unsigned r;
    asm("cvt.rna.tf32.f32 %0, %1;" : "=r"(r) : "f"(__uint_as_float(xbits)));
    return r;
}

__device__ __forceinline__ unsigned smem_u32(const void* p) {
    unsigned a;
    asm("{ .reg .u64 t; cvta.to.shared.u64 t, %1; cvt.u32.u64 %0, t; }"
        : "=r"(a) : "l"(p));
    return a;
}

__device__ __forceinline__ void cp16(unsigned dst, const void* src) {
    asm volatile("cp.async.cg.shared.global [%0], [%1], 16;" :: "r"(dst), "l"(src));
}
__device__ __forceinline__ void cp_commit() {
    asm volatile("cp.async.commit_group;");
}
template <int N>
__device__ __forceinline__ void cp_wait() {
    asm volatile("cp.async.wait_group %0;" :: "n"(N));
}

__device__ __forceinline__ void mma_tf32_16x8x8(float d[4],
                                                unsigned a0, unsigned a1, unsigned a2, unsigned a3,
                                                unsigned b0, unsigned b1) {
    asm volatile(
        "mma.sync.aligned.m16n8k8.row.col.f32.tf32.tf32.f32 "
        "{%0,%1,%2,%3}, {%4,%5,%6,%7}, {%8,%9}, {%0,%1,%2,%3};"
        : "+f"(d[0]), "+f"(d[1]), "+f"(d[2]), "+f"(d[3])
        : "r"(a0), "r"(a1), "r"(a2), "r"(a3), "r"(b0), "r"(b1));
}

// stage sizes (in 32-bit words)
#define ST_KM (32 * 132)   // [k][m] tile: 32 k-rows x 128 m (+4 pad) = 4224
#define ST_MK (128 * 36)   // [m][k] tile: 128 m-rows x 32 k (+4 pad) = 4608
#define NSTAGE 3

// ---------------------------------------------------------------------------
// GEMM1: score[b,i,j] = (1/32) * sum_c K[b,c,i] * Q[b,c,j]
//   A[m=i][k=c] = K[b,c,i] (m contiguous in gmem)  -> smem [k][m] stride 132
//   B[n=j][k=c] = Q[b,c,j] (n contiguous in gmem)  -> smem [k][n] stride 132
// CTA 128x128, KC=32 chunks, cp.async 3-stage pipeline, ONE barrier per iter.
// Fragment-load banks: addr=(kb+tg)*132 + r -> bank = 4*tg + g : conflict-free.
// ---------------------------------------------------------------------------
__global__ __launch_bounds__(256) void gemm1_kernel(const float* __restrict__ q,
                                                    const float* __restrict__ kk) {
    extern __shared__ unsigned sh[];
    unsigned* sA = sh;                    // NSTAGE * ST_KM
    unsigned* sB = sh + NSTAGE * ST_KM;   // NSTAGE * ST_KM

    const int b  = blockIdx.z;
    const int i0 = blockIdx.y * 128;
    const int j0 = blockIdx.x * 128;

    const int tid  = threadIdx.x;
    const int warp = tid >> 5, lane = tid & 31;
    const int wm = (warp & 1) * 64;
    const int wn = (warp >> 1) * 32;
    const int g  = lane >> 2, tg = lane & 3;

    const size_t base = (size_t)b * CDIM * LDIM;

    float acc[4][4][4];
#pragma unroll
    for (int mi = 0; mi < 4; ++mi)
#pragma unroll
        for (int ni = 0; ni < 4; ++ni)
#pragma unroll
            for (int e = 0; e < 4; ++e) acc[mi][ni][e] = 0.0f;

    // async copy of one 32-deep K chunk into stage st
    auto load_stage = [&](int st, int k0) {
#pragma unroll
        for (int it = 0; it < 4; ++it) {
            int c  = it * 256 + tid;      // 1024 16B-chunks per tensor
            int kc = c >> 5;              // 0..31
            int mc = (c & 31) * 4;        // 0,4,...,124 (words)
            cp16(smem_u32(&sA[st * ST_KM + kc * 132 + mc]),
                 &kk[base + (size_t)(k0 + kc) * LDIM + i0 + mc]);
            cp16(smem_u32(&sB[st * ST_KM + kc * 132 + mc]),
                 &q [base + (size_t)(k0 + kc) * LDIM + j0 + mc]);
        }
        cp_commit();
    };

    const int NIT = CDIM / 32;  // 16
    load_stage(0, 0);
    load_stage(1, 32);

    int cur = 0;   // stage being computed this iteration
    int nxt = 2;   // stage to load this iteration (= cur+2 mod 3)

    for (int it = 0; it < NIT; ++it) {
        if (it + 1 < NIT) cp_wait<1>(); else cp_wait<0>();
        __syncthreads();
        // Load stage it+2 (overwrites iter it-1's compute buffer: safe, all
        // warps passed this barrier only after finishing iter it-1 compute).
        if (it + 2 < NIT) load_stage(nxt, (it + 2) * 32);

        const unsigned* A  = &sA[cur * ST_KM];
        const unsigned* Bm = &sB[cur * ST_KM];
#pragma unroll
        for (int ks = 0; ks < 4; ++ks) {
            const int kb = ks * 8;
            unsigned af[4][4], bf[4][2];
            const unsigned* pa0 = &A[(kb + tg) * 132];
            const unsigned* pa4 = &A[(kb + tg + 4) * 132];
            const unsigned* pb0 = &Bm[(kb + tg) * 132];
            const unsigned* pb4 = &Bm[(kb + tg + 4) * 132];
#pragma unroll
            for (int mi = 0; mi < 4; ++mi) {
                int r = wm + mi * 16 + g;
                af[mi][0] = f2tf32(pa0[r]);
                af[mi][1] = f2tf32(pa0[r + 8]);
                af[mi][2] = f2tf32(pa4[r]);
                af[mi][3] = f2tf32(pa4[r + 8]);
            }
#pragma unroll
            for (int ni = 0; ni < 4; ++ni) {
                int c = wn + ni * 8 + g;
                bf[ni][0] = f2tf32(pb0[c]);
                bf[ni][1] = f2tf32(pb4[c]);
            }
#pragma unroll
            for (int mi = 0; mi < 4; ++mi)
#pragma unroll
                for (int ni = 0; ni < 4; ++ni)
                    mma_tf32_16x8x8(acc[mi][ni], af[mi][0], af[mi][1], af[mi][2], af[mi][3],
                                    bf[ni][0], bf[ni][1]);
        }
        cur = (cur == 2) ? 0 : cur + 1;
        nxt = (nxt == 2) ? 0 : nxt + 1;
    }

    const float scale = 0.03125f;  // 1/sqrt(1024)
    const size_t ob = (size_t)b * LDIM * LDIM;
#pragma unroll
    for (int mi = 0; mi < 4; ++mi) {
#pragma unroll
        for (int ni = 0; ni < 4; ++ni) {
            int r = i0 + wm + mi * 16 + g;
            int c = j0 + wn + ni * 8 + 2 * tg;
            float2 v0 = make_float2(acc[mi][ni][0] * scale, acc[mi][ni][1] * scale);
            float2 v1 = make_float2(acc[mi][ni][2] * scale, acc[mi][ni][3] * scale);
            *(float2*)&g_score[ob + (size_t)r * LDIM + c]       = v0;
            *(float2*)&g_score[ob + (size_t)(r + 8) * LDIM + c] = v1;
        }
    }
}

// ---------------------------------------------------------------------------
// Softmax over the BATCH axis (torch dim=None -> dim=0 for 3D). In-place.
// ---------------------------------------------------------------------------
__global__ __launch_bounds__(256) void softmax_b_kernel() {
    const size_t idx = (size_t)blockIdx.x * 256 + threadIdx.x;
    const size_t stride = (size_t)LDIM * LDIM;
    float s[BATCH];
    float mx = -1e30f;
#pragma unroll
    for (int b = 0; b < BATCH; ++b) {
        s[b] = g_score[(size_t)b * stride + idx];
        mx = fmaxf(mx, s[b]);
    }
    float sum = 0.0f;
#pragma unroll
    for (int b = 0; b < BATCH; ++b) {
        s[b] = expf(s[b] - mx);
        sum += s[b];
    }
    const float inv = 1.0f / sum;
#pragma unroll
    for (int b = 0; b < BATCH; ++b) g_score[(size_t)b * stride + idx] = s[b] * inv;
}

// ---------------------------------------------------------------------------
// GEMM2: out[b,c,j] = sum_i V[b,c,i] * W[b,i,j]
//   A[m=c][k=i] = V[b,c,i] (k contiguous in gmem) -> smem [m][k] stride 36
//   B[n=j][k=i] = W[b,i,j] (n contiguous in gmem) -> smem [k][n] stride 132
// ---------------------------------------------------------------------------
__global__ __launch_bounds__(256) void gemm2_kernel(const float* __restrict__ v,
                                                    float* __restrict__ out) {
    extern __shared__ unsigned sh[];
    unsigned* sA = sh;                    // NSTAGE * ST_MK  ([m][k])
    unsigned* sB = sh + NSTAGE * ST_MK;   // NSTAGE * ST_KM  ([k][n])

    const int b  = blockIdx.z;
    const int c0 = blockIdx.y * 128;
    const int j0 = blockIdx.x * 128;

    const int tid  = threadIdx.x;
    const int warp = tid >> 5, lane = tid & 31;
    const int wm = (warp & 1) * 64;
    const int wn = (warp >> 1) * 32;
    const int g  = lane >> 2, tg = lane & 3;

    const size_t vbase = (size_t)b * CDIM * LDIM;
    const size_t wbase = (size_t)b * LDIM * LDIM;

    float acc[4][4][4];
#pragma unroll
    for (int mi = 0; mi < 4; ++mi)
#pragma unroll
        for (int ni = 0; ni < 4; ++ni)
#pragma unroll
            for (int e = 0; e < 4; ++e) acc[mi][ni][e] = 0.0f;

    auto load_stage = [&](int st, int k0) {
#pragma unroll
        for (int it = 0; it < 4; ++it) {
            int c = it * 256 + tid;
            // A = V: [m][k], k contiguous in gmem. 128 rows x 8 chunks.
            int ma  = c >> 3;
            int ka4 = (c & 7) * 4;
            cp16(smem_u32(&sA[st * ST_MK + ma * 36 + ka4]),
                 &v[vbase + (size_t)(c0 + ma) * LDIM + k0 + ka4]);
            // B = W: [k][n], n contiguous in gmem. 32 rows x 32 chunks.
            int kc  = c >> 5;
            int nc4 = (c & 31) * 4;
            cp16(smem_u32(&sB[st * ST_KM + kc * 132 + nc4]),
                 &g_score[wbase + (size_t)(k0 + kc) * LDIM + j0 + nc4]);
        }
        cp_commit();
    };

    const int NIT = LDIM / 32;  // 32
    load_stage(0, 0);
    load_stage(1, 32);

    int cur = 0;
    int nxt = 2;

    for (int it = 0; it < NIT; ++it) {
        if (it + 1 < NIT) cp_wait<1>(); else cp_wait<0>();
        __syncthreads();
        if (it + 2 < NIT) load_stage(nxt, (it + 2) * 32);

        const unsigned* A  = &sA[cur * ST_MK];
        const unsigned* Bm = &sB[cur * ST_KM];
#pragma unroll
        for (int ks = 0; ks < 4; ++ks) {
            const int kb = ks * 8;
            unsigned af[4][4], bf[4][2];
            const unsigned* pb0 = &Bm[(kb + tg) * 132];
            const unsigned* pb4 = &Bm[(kb + tg + 4) * 132];
#pragma unroll
            for (int mi = 0; mi < 4; ++mi) {
                int r = wm + mi * 16 + g;
                af[mi][0] = f2tf32(A[r * 36 + kb + tg]);
                af[mi][1] = f2tf32(A[(r + 8) * 36 + kb + tg]);
                af[mi][2] = f2tf32(A[r * 36 + kb + tg + 4]);
                af[mi][3] = f2tf32(A[(r + 8) * 36 + kb + tg + 4]);
            }
#pragma unroll
            for (int ni = 0; ni < 4; ++ni) {
                int c = wn + ni * 8 + g;
                bf[ni][0] = f2tf32(pb0[c]);
                bf[ni][1] = f2tf32(pb4[c]);
            }
#pragma unroll
            for (int mi = 0; mi < 4; ++mi)
#pragma unroll
                for (int ni = 0; ni < 4; ++ni)
                    mma_tf32_16x8x8(acc[mi][ni], af[mi][0], af[mi][1], af[mi][2], af[mi][3],
                                    bf[ni][0], bf[ni][1]);
        }
        cur = (cur == 2) ? 0 : cur + 1;
        nxt = (nxt == 2) ? 0 : nxt + 1;
    }

    const size_t obase = (size_t)b * CDIM * LDIM;
#pragma unroll
    for (int mi = 0; mi < 4; ++mi) {
#pragma unroll
        for (int ni = 0; ni < 4; ++ni) {
            int r = c0 + wm + mi * 16 + g;
            int c = j0 + wn + ni * 8 + 2 * tg;
            float2 v0 = make_float2(acc[mi][ni][0], acc[mi][ni][1]);
            float2 v1 = make_float2(acc[mi][ni][2], acc[mi][ni][3]);
            *(float2*)&out[obase + (size_t)r * LDIM + c]       = v0;
            *(float2*)&out[obase + (size_t)(r + 8) * LDIM + c] = v1;
        }
    }
}

extern "C" void kernel_launch(void* const* d_in, const int* in_sizes, int n_in,
                              void* d_out, int out_size) {
    const float* q = (const float*)d_in[0];
    const float* k = (const float*)d_in[1];
    const float* v = (const float*)d_in[2];
    float* out = (float*)d_out;

    const int smem1 = NSTAGE * 2 * ST_KM * 4;             // 101376 B
    const int smem2 = NSTAGE * (ST_MK + ST_KM) * 4;       // 105984 B
    cudaFuncSetAttribute(gemm1_kernel, cudaFuncAttributeMaxDynamicSharedMemorySize, smem1);
    cudaFuncSetAttribute(gemm2_kernel, cudaFuncAttributeMaxDynamicSharedMemorySize, smem2);

    gemm1_kernel<<<dim3(LDIM / 128, LDIM / 128, BATCH), 256, smem1>>>(q, k);
    softmax_b_kernel<<<(LDIM * LDIM) / 256, 256>>>();
    gemm2_kernel<<<dim3(LDIM / 128, CDIM / 128, BATCH), 256, smem2>>>(v, out);
}

// round 7
// speedup vs baseline: 1.0594x; 1.0594x over previous
#include <cuda_runtime.h>
#include <math.h>

// q,k,v : (B=16, C=512, L=1024) fp32
// score[b,i,j] = sum_c k[b,c,i]*q[b,c,j] / 32 ; w = softmax over BATCH axis ;
// out[b,c,j] = sum_i v[b,c,i]*w[b,i,j]

#define BATCH 16
#define CDIM  512
#define LDIM  1024

// Scratch (device globals: allocation-free). 160 MB total.
__device__ float g_score[(size_t)BATCH * LDIM * LDIM];   // logits -> weights (tf32-rounded)
__device__ float g_qr[(size_t)BATCH * CDIM * LDIM];      // tf32-rounded Q
__device__ float g_kr[(size_t)BATCH * CDIM * LDIM];      // tf32-rounded K
__device__ float g_vr[(size_t)BATCH * CDIM * LDIM];      // tf32-rounded V

// ---------------- PTX helpers ----------------
__device__ __forceinline__ unsigned f2tf32(unsigned xbits) {
    unsigned r;
    asm("cvt.rna.tf32.f32 %0, %1;" : "=r"(r) : "f"(__uint_as_float(xbits)));
    return r;
}

__device__ __forceinline__ unsigned smem_u32(const void* p) {
    unsigned a;
    asm("{ .reg .u64 t; cvta.to.shared.u64 t, %1; cvt.u32.u64 %0, t; }"
        : "=r"(a) : "l"(p));
    return a;
}

__device__ __forceinline__ void cp16(unsigned dst, const void* src) {
    asm volatile("cp.async.cg.shared.global [%0], [%1], 16;" :: "r"(dst), "l"(src));
}
__device__ __forceinline__ void cp_commit() {
    asm volatile("cp.async.commit_group;");
}
template <int N>
__device__ __forceinline__ void cp_wait() {
    asm volatile("cp.async.wait_group %0;" :: "n"(N));
}

__device__ __forceinline__ void mma_tf32_16x8x8(float d[4],
                                                unsigned a0, unsigned a1, unsigned a2, unsigned a3,
                                                unsigned b0, unsigned b1) {
    asm volatile(
        "mma.sync.aligned.m16n8k8.row.col.f32.tf32.tf32.f32 "
        "{%0,%1,%2,%3}, {%4,%5,%6,%7}, {%8,%9}, {%0,%1,%2,%3};"
        : "+f"(d[0]), "+f"(d[1]), "+f"(d[2]), "+f"(d[3])
        : "r"(a0), "r"(a1), "r"(a2), "r"(a3), "r"(b0), "r"(b1));
}

// stage sizes (in 32-bit words)
#define ST_KM (32 * 132)   // [k][m] tile: 32 k-rows x 128 m (+4 pad) = 4224
#define ST_MK (128 * 36)   // [m][k] tile: 128 m-rows x 32 k (+4 pad) = 4608
#define NSTAGE 3

// ---------------------------------------------------------------------------
// Prologue: round q,k,v to tf32 (rna) once. Removes all inner-loop cvts from
// the GEMMs (mathematically identical rounding to the previous version).
// ---------------------------------------------------------------------------
__global__ __launch_bounds__(256) void round3_kernel(const float4* __restrict__ q,
                                                     const float4* __restrict__ k,
                                                     const float4* __restrict__ v) {
    const int i = blockIdx.x * 256 + threadIdx.x;  // over 2,097,152 float4 per tensor
    float4* qo = (float4*)g_qr;
    float4* ko = (float4*)g_kr;
    float4* vo = (float4*)g_vr;
    float4 a = q[i], b = k[i], c = v[i];
#define RND(x) __uint_as_float(f2tf32(__float_as_uint(x)))
    qo[i] = make_float4(RND(a.x), RND(a.y), RND(a.z), RND(a.w));
    ko[i] = make_float4(RND(b.x), RND(b.y), RND(b.z), RND(b.w));
    vo[i] = make_float4(RND(c.x), RND(c.y), RND(c.z), RND(c.w));
#undef RND
}

// ---------------------------------------------------------------------------
// GEMM1: score[b,i,j] = (1/32) * sum_c K[b,c,i] * Q[b,c,j]
//   A[m=i][k=c] = Kr[b,c,i] (m contiguous) -> smem [k][m] stride 132
//   B[n=j][k=c] = Qr[b,c,j] (n contiguous) -> smem [k][n] stride 132
// CTA 128x128, 4 warps (2x2 of 64x64 warp tiles), KC=32 chunks,
// 3-stage cp.async pipeline, ONE barrier per iter. Data pre-rounded: no cvt.
// Fragment banks: addr=(kb+tg)*132 + r -> bank = (4*tg + g) mod 32 : conflict-free.
// ---------------------------------------------------------------------------
__global__ __launch_bounds__(128) void gemm1_kernel() {
    extern __shared__ unsigned sh[];
    unsigned* sA = sh;                    // NSTAGE * ST_KM
    unsigned* sB = sh + NSTAGE * ST_KM;   // NSTAGE * ST_KM

    const int b  = blockIdx.z;
    const int i0 = blockIdx.y * 128;
    const int j0 = blockIdx.x * 128;

    const int tid  = threadIdx.x;
    const int warp = tid >> 5, lane = tid & 31;
    const int wm = (warp & 1) * 64;    // 2x2 warp grid of 64x64 tiles
    const int wn = (warp >> 1) * 64;
    const int g  = lane >> 2, tg = lane & 3;

    const size_t base = (size_t)b * CDIM * LDIM;
    const float* kr = g_kr + base;
    const float* qr = g_qr + base;

    float acc[4][8][4];
#pragma unroll
    for (int mi = 0; mi < 4; ++mi)
#pragma unroll
        for (int ni = 0; ni < 8; ++ni)
#pragma unroll
            for (int e = 0; e < 4; ++e) acc[mi][ni][e] = 0.0f;

    // async copy of one 32-deep K chunk into stage st (1024 chunks per operand)
    auto load_stage = [&](int st, int k0) {
#pragma unroll
        for (int it = 0; it < 8; ++it) {
            int c  = it * 128 + tid;
            int kc = c >> 5;              // 0..31
            int mc = (c & 31) * 4;        // 0,4,...,124 (words)
            cp16(smem_u32(&sA[st * ST_KM + kc * 132 + mc]),
                 &kr[(size_t)(k0 + kc) * LDIM + i0 + mc]);
            cp16(smem_u32(&sB[st * ST_KM + kc * 132 + mc]),
                 &qr[(size_t)(k0 + kc) * LDIM + j0 + mc]);
        }
        cp_commit();
    };

    const int NIT = CDIM / 32;  // 16
    load_stage(0, 0);
    load_stage(1, 32);

    int cur = 0;   // stage being computed
    int nxt = 2;   // stage to load this iteration

    for (int it = 0; it < NIT; ++it) {
        if (it + 1 < NIT) cp_wait<1>(); else cp_wait<0>();
        __syncthreads();
        if (it + 2 < NIT) load_stage(nxt, (it + 2) * 32);

        const unsigned* A  = &sA[cur * ST_KM];
        const unsigned* Bm = &sB[cur * ST_KM];
#pragma unroll
        for (int ks = 0; ks < 4; ++ks) {
            const int kb = ks * 8;
            unsigned af[4][4], bf[8][2];
            const unsigned* pa0 = &A[(kb + tg) * 132];
            const unsigned* pa4 = &A[(kb + tg + 4) * 132];
            const unsigned* pb0 = &Bm[(kb + tg) * 132];
            const unsigned* pb4 = &Bm[(kb + tg + 4) * 132];
#pragma unroll
            for (int mi = 0; mi < 4; ++mi) {
                int r = wm + mi * 16 + g;
                af[mi][0] = pa0[r];
                af[mi][1] = pa0[r + 8];
                af[mi][2] = pa4[r];
                af[mi][3] = pa4[r + 8];
            }
#pragma unroll
            for (int ni = 0; ni < 8; ++ni) {
                int c = wn + ni * 8 + g;
                bf[ni][0] = pb0[c];
                bf[ni][1] = pb4[c];
            }
#pragma unroll
            for (int mi = 0; mi < 4; ++mi)
#pragma unroll
                for (int ni = 0; ni < 8; ++ni)
                    mma_tf32_16x8x8(acc[mi][ni], af[mi][0], af[mi][1], af[mi][2], af[mi][3],
                                    bf[ni][0], bf[ni][1]);
        }
        cur = (cur == 2) ? 0 : cur + 1;
        nxt = (nxt == 2) ? 0 : nxt + 1;
    }

    const float scale = 0.03125f;  // 1/sqrt(1024)
    const size_t ob = (size_t)b * LDIM * LDIM;
#pragma unroll
    for (int mi = 0; mi < 4; ++mi) {
#pragma unroll
        for (int ni = 0; ni < 8; ++ni) {
            int r = i0 + wm + mi * 16 + g;
            int c = j0 + wn + ni * 8 + 2 * tg;
            float2 v0 = make_float2(acc[mi][ni][0] * scale, acc[mi][ni][1] * scale);
            float2 v1 = make_float2(acc[mi][ni][2] * scale, acc[mi][ni][3] * scale);
            *(float2*)&g_score[ob + (size_t)r * LDIM + c]       = v0;
            *(float2*)&g_score[ob + (size_t)(r + 8) * LDIM + c] = v1;
        }
    }
}

// ---------------------------------------------------------------------------
// Softmax over the BATCH axis (torch dim=None -> dim=0 for 3D). In-place.
// Output weights are tf32-rounded here (free), so GEMM2 needs no inner cvt.
// ---------------------------------------------------------------------------
__global__ __launch_bounds__(256) void softmax_b_kernel() {
    const size_t idx = (size_t)blockIdx.x * 256 + threadIdx.x;
    const size_t stride = (size_t)LDIM * LDIM;
    float s[BATCH];
    float mx = -1e30f;
#pragma unroll
    for (int b = 0; b < BATCH; ++b) {
        s[b] = g_score[(size_t)b * stride + idx];
        mx = fmaxf(mx, s[b]);
    }
    float sum = 0.0f;
#pragma unroll
    for (int b = 0; b < BATCH; ++b) {
        s[b] = expf(s[b] - mx);
        sum += s[b];
    }
    const float inv = 1.0f / sum;
#pragma unroll
    for (int b = 0; b < BATCH; ++b)
        g_score[(size_t)b * stride + idx] =
            __uint_as_float(f2tf32(__float_as_uint(s[b] * inv)));
}

// ---------------------------------------------------------------------------
// GEMM2: out[b,c,j] = sum_i V[b,c,i] * W[b,i,j]
//   A[m=c][k=i] = Vr[b,c,i] (k contiguous) -> smem [m][k] stride 36
//   B[n=j][k=i] = W[b,i,j]  (n contiguous) -> smem [k][n] stride 132
// CTA 128x128, 4 warps of 64x64. Data pre-rounded: no inner cvt.
// ---------------------------------------------------------------------------
__global__ __launch_bounds__(128) void gemm2_kernel(float* __restrict__ out) {
    extern __shared__ unsigned sh[];
    unsigned* sA = sh;                    // NSTAGE * ST_MK  ([m][k])
    unsigned* sB = sh + NSTAGE * ST_MK;   // NSTAGE * ST_KM  ([k][n])

    const int b  = blockIdx.z;
    const int c0 = blockIdx.y * 128;
    const int j0 = blockIdx.x * 128;

    const int tid  = threadIdx.x;
    const int warp = tid >> 5, lane = tid & 31;
    const int wm = (warp & 1) * 64;
    const int wn = (warp >> 1) * 64;
    const int g  = lane >> 2, tg = lane & 3;

    const float* vr = g_vr + (size_t)b * CDIM * LDIM;
    const float* wS = g_score + (size_t)b * LDIM * LDIM;

    float acc[4][8][4];
#pragma unroll
    for (int mi = 0; mi < 4; ++mi)
#pragma unroll
        for (int ni = 0; ni < 8; ++ni)
#pragma unroll
            for (int e = 0; e < 4; ++e) acc[mi][ni][e] = 0.0f;

    auto load_stage = [&](int st, int k0) {
#pragma unroll
        for (int it = 0; it < 8; ++it) {
            int c = it * 128 + tid;
            // A = V: [m][k], k contiguous in gmem. 128 rows x 8 chunks.
            int ma  = c >> 3;
            int ka4 = (c & 7) * 4;
            cp16(smem_u32(&sA[st * ST_MK + ma * 36 + ka4]),
                 &vr[(size_t)(c0 + ma) * LDIM + k0 + ka4]);
            // B = W: [k][n], n contiguous in gmem. 32 rows x 32 chunks.
            int kc  = c >> 5;
            int nc4 = (c & 31) * 4;
            cp16(smem_u32(&sB[st * ST_KM + kc * 132 + nc4]),
                 &wS[(size_t)(k0 + kc) * LDIM + j0 + nc4]);
        }
        cp_commit();
    };

    const int NIT = LDIM / 32;  // 32
    load_stage(0, 0);
    load_stage(1, 32);

    int cur = 0;
    int nxt = 2;

    for (int it = 0; it < NIT; ++it) {
        if (it + 1 < NIT) cp_wait<1>(); else cp_wait<0>();
        __syncthreads();
        if (it + 2 < NIT) load_stage(nxt, (it + 2) * 32);

        const unsigned* A  = &sA[cur * ST_MK];
        const unsigned* Bm = &sB[cur * ST_KM];
#pragma unroll
        for (int ks = 0; ks < 4; ++ks) {
            const int kb = ks * 8;
            unsigned af[4][4], bf[8][2];
            const unsigned* pb0 = &Bm[(kb + tg) * 132];
            const unsigned* pb4 = &Bm[(kb + tg + 4) * 132];
#pragma unroll
            for (int mi = 0; mi < 4; ++mi) {
                int r = wm + mi * 16 + g;
                af[mi][0] = A[r * 36 + kb + tg];
                af[mi][1] = A[(r + 8) * 36 + kb + tg];
                af[mi][2] = A[r * 36 + kb + tg + 4];
                af[mi][3] = A[(r + 8) * 36 + kb + tg + 4];
            }
#pragma unroll
            for (int ni = 0; ni < 8; ++ni) {
                int c = wn + ni * 8 + g;
                bf[ni][0] = pb0[c];
                bf[ni][1] = pb4[c];
            }
#pragma unroll
            for (int mi = 0; mi < 4; ++mi)
#pragma unroll
                for (int ni = 0; ni < 8; ++ni)
                    mma_tf32_16x8x8(acc[mi][ni], af[mi][0], af[mi][1], af[mi][2], af[mi][3],
                                    bf[ni][0], bf[ni][1]);
        }
        cur = (cur == 2) ? 0 : cur + 1;
        nxt = (nxt == 2) ? 0 : nxt + 1;
    }

    const size_t obase = (size_t)b * CDIM * LDIM;
#pragma unroll
    for (int mi = 0; mi < 4; ++mi) {
#pragma unroll
        for (int ni = 0; ni < 8; ++ni) {
            int r = c0 + wm + mi * 16 + g;
            int c = j0 + wn + ni * 8 + 2 * tg;
            float2 v0 = make_float2(acc[mi][ni][0], acc[mi][ni][1]);
            float2 v1 = make_float2(acc[mi][ni][2], acc[mi][ni][3]);
            *(float2*)&out[obase + (size_t)r * LDIM + c]       = v0;
            *(float2*)&out[obase + (size_t)(r + 8) * LDIM + c] = v1;
        }
    }
}

extern "C" void kernel_launch(void* const* d_in, const int* in_sizes, int n_in,
                              void* d_out, int out_size) {
    const float* q = (const float*)d_in[0];
    const float* k = (const float*)d_in[1];
    const float* v = (const float*)d_in[2];
    float* out = (float*)d_out;

    const int smem1 = NSTAGE * 2 * ST_KM * 4;             // 101376 B
    const int smem2 = NSTAGE * (ST_MK + ST_KM) * 4;       // 105984 B
    cudaFuncSetAttribute(gemm1_kernel, cudaFuncAttributeMaxDynamicSharedMemorySize, smem1);
    cudaFuncSetAttribute(gemm2_kernel, cudaFuncAttributeMaxDynamicSharedMemorySize, smem2);

    // Prologue: tf32-round q,k,v (2,097,152 float4 per tensor)
    round3_kernel<<<(BATCH * CDIM * LDIM / 4) / 256, 256>>>(
        (const float4*)q, (const float4*)k, (const float4*)v);
    // GEMM1: score tiles
    gemm1_kernel<<<dim3(LDIM / 128, LDIM / 128, BATCH), 128, smem1>>>();
    // Batch softmax (+ tf32 rounding of weights)
    softmax_b_kernel<<<(LDIM * LDIM) / 256, 256>>>();
    // GEMM2: out tiles
    gemm2_kernel<<<dim3(LDIM / 128, CDIM / 128, BATCH), 128, smem2>>>(out);
}

// round 15
// speedup vs baseline: 1.1234x; 1.0604x over previous
#include <cuda_runtime.h>
#include <math.h>

// q,k,v : (B=16, C=512, L=1024) fp32
// score[b,i,j] = sum_c k[b,c,i]*q[b,c,j] / 32 ; w = softmax over BATCH axis ;
// out[b,c,j] = sum_i v[b,c,i]*w[b,i,j]

#define BATCH 16
#define CDIM  512
#define LDIM  1024

// Scratch (device globals: allocation-free). 160 MB total.
__device__ float g_score[(size_t)BATCH * LDIM * LDIM];   // logits -> weights (tf32-rounded)
__device__ float g_qr[(size_t)BATCH * CDIM * LDIM];      // tf32-rounded Q
__device__ float g_kr[(size_t)BATCH * CDIM * LDIM];      // tf32-rounded K
__device__ float g_vr[(size_t)BATCH * CDIM * LDIM];      // tf32-rounded V

// ---------------- PTX helpers ----------------
__device__ __forceinline__ unsigned f2tf32(unsigned xbits) {
    unsigned r;
    asm("cvt.rna.tf32.f32 %0, %1;" : "=r"(r) : "f"(__uint_as_float(xbits)));
    return r;
}

__device__ __forceinline__ unsigned smem_u32(const void* p) {
    unsigned a;
    asm("{ .reg .u64 t; cvta.to.shared.u64 t, %1; cvt.u32.u64 %0, t; }"
        : "=r"(a) : "l"(p));
    return a;
}

__device__ __forceinline__ void cp16(unsigned dst, const void* src) {
    asm volatile("cp.async.cg.shared.global [%0], [%1], 16;" :: "r"(dst), "l"(src));
}
__device__ __forceinline__ void cp_commit() {
    asm volatile("cp.async.commit_group;");
}
template <int N>
__device__ __forceinline__ void cp_wait() {
    asm volatile("cp.async.wait_group %0;" :: "n"(N));
}

__device__ __forceinline__ void mma_tf32_16x8x8(float d[4],
                                                unsigned a0, unsigned a1, unsigned a2, unsigned a3,
                                                unsigned b0, unsigned b1) {
    asm volatile(
        "mma.sync.aligned.m16n8k8.row.col.f32.tf32.tf32.f32 "
        "{%0,%1,%2,%3}, {%4,%5,%6,%7}, {%8,%9}, {%0,%1,%2,%3};"
        : "+f"(d[0]), "+f"(d[1]), "+f"(d[2]), "+f"(d[3])
        : "r"(a0), "r"(a1), "r"(a2), "r"(a3), "r"(b0), "r"(b1));
}

// stage sizes (in 32-bit words)
#define ST_KM (32 * 132)   // [k][m] tile: 32 k-rows x 128 m (+4 pad) = 4224
#define ST_MK (128 * 36)   // [m][k] tile: 128 m-rows x 32 k (+4 pad) = 4608
#define NSTAGE 2           // 2 stages -> smem <= 71KB -> 2 CTAs/SM resident

// ---------------------------------------------------------------------------
// Prologue: round q,k,v to tf32 (rna) once. Removes all inner-loop cvts from
// the GEMMs (mathematically identical rounding to doing it per-fragment).
// ---------------------------------------------------------------------------
__global__ __launch_bounds__(256) void round3_kernel(const float4* __restrict__ q,
                                                     const float4* __restrict__ k,
                                                     const float4* __restrict__ v) {
    const int i = blockIdx.x * 256 + threadIdx.x;  // over 2,097,152 float4 per tensor
    float4* qo = (float4*)g_qr;
    float4* ko = (float4*)g_kr;
    float4* vo = (float4*)g_vr;
    float4 a = q[i], b = k[i], c = v[i];
#define RND(x) __uint_as_float(f2tf32(__float_as_uint(x)))
    qo[i] = make_float4(RND(a.x), RND(a.y), RND(a.z), RND(a.w));
    ko[i] = make_float4(RND(b.x), RND(b.y), RND(b.z), RND(b.w));
    vo[i] = make_float4(RND(c.x), RND(c.y), RND(c.z), RND(c.w));
#undef RND
}

// ---------------------------------------------------------------------------
// GEMM1: score[b,i,j] = (1/32) * sum_c K[b,c,i] * Q[b,c,j]
//   A[m=i][k=c] = Kr[b,c,i] (m contiguous) -> smem [k][m] stride 132
//   B[n=j][k=c] = Qr[b,c,j] (n contiguous) -> smem [k][n] stride 132
// CTA 128x128, 4 warps (2x2 of 64x64 warp tiles), KC=32 chunks,
// 2-stage cp.async double buffer, ONE barrier per iter:
//   iter it: wait g(it) [only pending], barrier, commit g(it+1) into buffer
//   (it+1)%2 (= the it-1 compute buffer: safe past the barrier), compute it.
// Fragment banks: addr=(kb+tg)*132 + r -> bank = (4*tg + g) mod 32 : conflict-free.
// ---------------------------------------------------------------------------
__global__ __launch_bounds__(128) void gemm1_kernel() {
    extern __shared__ unsigned sh[];
    unsigned* sA = sh;                    // NSTAGE * ST_KM
    unsigned* sB = sh + NSTAGE * ST_KM;   // NSTAGE * ST_KM

    const int b  = blockIdx.z;
    const int i0 = blockIdx.y * 128;
    const int j0 = blockIdx.x * 128;

    const int tid  = threadIdx.x;
    const int warp = tid >> 5, lane = tid & 31;
    const int wm = (warp & 1) * 64;    // 2x2 warp grid of 64x64 tiles
    const int wn = (warp >> 1) * 64;
    const int g  = lane >> 2, tg = lane & 3;

    const size_t base = (size_t)b * CDIM * LDIM;
    const float* kr = g_kr + base;
    const float* qr = g_qr + base;

    float acc[4][8][4];
#pragma unroll
    for (int mi = 0; mi < 4; ++mi)
#pragma unroll
        for (int ni = 0; ni < 8; ++ni)
#pragma unroll
            for (int e = 0; e < 4; ++e) acc[mi][ni][e] = 0.0f;

    // async copy of one 32-deep K chunk into stage st (1024 chunks per operand)
    auto load_stage = [&](int st, int k0) {
#pragma unroll
        for (int it = 0; it < 8; ++it) {
            int c  = it * 128 + tid;
            int kc = c >> 5;              // 0..31
            int mc = (c & 31) * 4;        // 0,4,...,124 (words)
            cp16(smem_u32(&sA[st * ST_KM + kc * 132 + mc]),
                 &kr[(size_t)(k0 + kc) * LDIM + i0 + mc]);
            cp16(smem_u32(&sB[st * ST_KM + kc * 132 + mc]),
                 &qr[(size_t)(k0 + kc) * LDIM + j0 + mc]);
        }
        cp_commit();
    };

    const int NIT = CDIM / 32;  // 16
    load_stage(0, 0);
    int cur = 0;

    for (int it = 0; it < NIT; ++it) {
        cp_wait<0>();          // only g(it) pending here
        __syncthreads();       // all warps done with buffer cur^1 (iter it-1)
        if (it + 1 < NIT) load_stage(cur ^ 1, (it + 1) * 32);

        const unsigned* A  = &sA[cur * ST_KM];
        const unsigned* Bm = &sB[cur * ST_KM];
#pragma unroll
        for (int ks = 0; ks < 4; ++ks) {
            const int kb = ks * 8;
            unsigned af[4][4], bf[8][2];
            const unsigned* pa0 = &A[(kb + tg) * 132];
            const unsigned* pa4 = &A[(kb + tg + 4) * 132];
            const unsigned* pb0 = &Bm[(kb + tg) * 132];
            const unsigned* pb4 = &Bm[(kb + tg + 4) * 132];
#pragma unroll
            for (int mi = 0; mi < 4; ++mi) {
                int r = wm + mi * 16 + g;
                af[mi][0] = pa0[r];
                af[mi][1] = pa0[r + 8];
                af[mi][2] = pa4[r];
                af[mi][3] = pa4[r + 8];
            }
#pragma unroll
            for (int ni = 0; ni < 8; ++ni) {
                int c = wn + ni * 8 + g;
                bf[ni][0] = pb0[c];
                bf[ni][1] = pb4[c];
            }
#pragma unroll
            for (int mi = 0; mi < 4; ++mi)
#pragma unroll
                for (int ni = 0; ni < 8; ++ni)
                    mma_tf32_16x8x8(acc[mi][ni], af[mi][0], af[mi][1], af[mi][2], af[mi][3],
                                    bf[ni][0], bf[ni][1]);
        }
        cur ^= 1;
    }

    const float scale = 0.03125f;  // 1/sqrt(1024)
    const size_t ob = (size_t)b * LDIM * LDIM;
#pragma unroll
    for (int mi = 0; mi < 4; ++mi) {
#pragma unroll
        for (int ni = 0; ni < 8; ++ni) {
            int r = i0 + wm + mi * 16 + g;
            int c = j0 + wn + ni * 8 + 2 * tg;
            float2 v0 = make_float2(acc[mi][ni][0] * scale, acc[mi][ni][1] * scale);
            float2 v1 = make_float2(acc[mi][ni][2] * scale, acc[mi][ni][3] * scale);
            *(float2*)&g_score[ob + (size_t)r * LDIM + c]       = v0;
            *(float2*)&g_score[ob + (size_t)(r + 8) * LDIM + c] = v1;
        }
    }
}

// ---------------------------------------------------------------------------
// Softmax over the BATCH axis (torch dim=None -> dim=0 for 3D). In-place.
// Output weights tf32-rounded here (free) so GEMM2 needs no inner cvt.
// ---------------------------------------------------------------------------
__global__ __launch_bounds__(256) void softmax_b_kernel() {
    const size_t idx = (size_t)blockIdx.x * 256 + threadIdx.x;
    const size_t stride = (size_t)LDIM * LDIM;
    float s[BATCH];
    float mx = -1e30f;
#pragma unroll
    for (int b = 0; b < BATCH; ++b) {
        s[b] = g_score[(size_t)b * stride + idx];
        mx = fmaxf(mx, s[b]);
    }
    float sum = 0.0f;
#pragma unroll
    for (int b = 0; b < BATCH; ++b) {
        s[b] = expf(s[b] - mx);
        sum += s[b];
    }
    const float inv = 1.0f / sum;
#pragma unroll
    for (int b = 0; b < BATCH; ++b)
        g_score[(size_t)b * stride + idx] =
            __uint_as_float(f2tf32(__float_as_uint(s[b] * inv)));
}

// ---------------------------------------------------------------------------
// GEMM2: out[b,c,j] = sum_i V[b,c,i] * W[b,i,j]
//   A[m=c][k=i] = Vr[b,c,i] (k contiguous) -> smem [m][k] stride 36
//   B[n=j][k=i] = W[b,i,j]  (n contiguous) -> smem [k][n] stride 132
// CTA 128x128, 4 warps of 64x64, 2-stage double buffer.
// ---------------------------------------------------------------------------
__global__ __launch_bounds__(128) void gemm2_kernel(float* __restrict__ out) {
    extern __shared__ unsigned sh[];
    unsigned* sA = sh;                    // NSTAGE * ST_MK  ([m][k])
    unsigned* sB = sh + NSTAGE * ST_MK;   // NSTAGE * ST_KM  ([k][n])

    const int b  = blockIdx.z;
    const int c0 = blockIdx.y * 128;
    const int j0 = blockIdx.x * 128;

    const int tid  = threadIdx.x;
    const int warp = tid >> 5, lane = tid & 31;
    const int wm = (warp & 1) * 64;
    const int wn = (warp >> 1) * 64;
    const int g  = lane >> 2, tg = lane & 3;

    const float* vr = g_vr + (size_t)b * CDIM * LDIM;
    const float* wS = g_score + (size_t)b * LDIM * LDIM;

    float acc[4][8][4];
#pragma unroll
    for (int mi = 0; mi < 4; ++mi)
#pragma unroll
        for (int ni = 0; ni < 8; ++ni)
#pragma unroll
            for (int e = 0; e < 4; ++e) acc[mi][ni][e] = 0.0f;

    auto load_stage = [&](int st, int k0) {
#pragma unroll
        for (int it = 0; it < 8; ++it) {
            int c = it * 128 + tid;
            // A = V: [m][k], k contiguous in gmem. 128 rows x 8 chunks.
            int ma  = c >> 3;
            int ka4 = (c & 7) * 4;
            cp16(smem_u32(&sA[st * ST_MK + ma * 36 + ka4]),
                 &vr[(size_t)(c0 + ma) * LDIM + k0 + ka4]);
            // B = W: [k][n], n contiguous in gmem. 32 rows x 32 chunks.
            int kc  = c >> 5;
            int nc4 = (c & 31) * 4;
            cp16(smem_u32(&sB[st * ST_KM + kc * 132 + nc4]),
                 &wS[(size_t)(k0 + kc) * LDIM + j0 + nc4]);
        }
        cp_commit();
    };

    const int NIT = LDIM / 32;  // 32
    load_stage(0, 0);
    int cur = 0;

    for (int it = 0; it < NIT; ++it) {
        cp_wait<0>();
        __syncthreads();
        if (it + 1 < NIT) load_stage(cur ^ 1, (it + 1) * 32);

        const unsigned* A  = &sA[cur * ST_MK];
        const unsigned* Bm = &sB[cur * ST_KM];
#pragma unroll
        for (int ks = 0; ks < 4; ++ks) {
            const int kb = ks * 8;
            unsigned af[4][4], bf[8][2];
            const unsigned* pb0 = &Bm[(kb + tg) * 132];
            const unsigned* pb4 = &Bm[(kb + tg + 4) * 132];
#pragma unroll
            for (int mi = 0; mi < 4; ++mi) {
                int r = wm + mi * 16 + g;
                af[mi][0] = A[r * 36 + kb + tg];
                af[mi][1] = A[(r + 8) * 36 + kb + tg];
                af[mi][2] = A[r * 36 + kb + tg + 4];
                af[mi][3] = A[(r + 8) * 36 + kb + tg + 4];
            }
#pragma unroll
            for (int ni = 0; ni < 8; ++ni) {
                int c = wn + ni * 8 + g;
                bf[ni][0] = pb0[c];
                bf[ni][1] = pb4[c];
            }
#pragma unroll
            for (int mi = 0; mi < 4; ++mi)
#pragma unroll
                for (int ni = 0; ni < 8; ++ni)
                    mma_tf32_16x8x8(acc[mi][ni], af[mi][0], af[mi][1], af[mi][2], af[mi][3],
                                    bf[ni][0], bf[ni][1]);
        }
        cur ^= 1;
    }

    const size_t obase = (size_t)b * CDIM * LDIM;
#pragma unroll
    for (int mi = 0; mi < 4; ++mi) {
#pragma unroll
        for (int ni = 0; ni < 8; ++ni) {
            int r = c0 + wm + mi * 16 + g;
            int c = j0 + wn + ni * 8 + 2 * tg;
            float2 v0 = make_float2(acc[mi][ni][0], acc[mi][ni][1]);
            float2 v1 = make_float2(acc[mi][ni][2], acc[mi][ni][3]);
            *(float2*)&out[obase + (size_t)r * LDIM + c]       = v0;
            *(float2*)&out[obase + (size_t)(r + 8) * LDIM + c] = v1;
        }
    }
}

extern "C" void kernel_launch(void* const* d_in, const int* in_sizes, int n_in,
                              void* d_out, int out_size) {
    const float* q = (const float*)d_in[0];
    const float* k = (const float*)d_in[1];
    const float* v = (const float*)d_in[2];
    float* out = (float*)d_out;

    const int smem1 = NSTAGE * 2 * ST_KM * 4;             // 67584 B  -> 2+ CTAs/SM
    const int smem2 = NSTAGE * (ST_MK + ST_KM) * 4;       // 70656 B  -> 2 CTAs/SM
    cudaFuncSetAttribute(gemm1_kernel, cudaFuncAttributeMaxDynamicSharedMemorySize, smem1);
    cudaFuncSetAttribute(gemm2_kernel, cudaFuncAttributeMaxDynamicSharedMemorySize, smem2);

    // Prologue: tf32-round q,k,v (2,097,152 float4 per tensor)
    round3_kernel<<<(BATCH * CDIM * LDIM / 4) / 256, 256>>>(
        (const float4*)q, (const float4*)k, (const float4*)v);
    // GEMM1: score tiles
    gemm1_kernel<<<dim3(LDIM / 128, LDIM / 128, BATCH), 128, smem1>>>();
    // Batch softmax (+ tf32 rounding of weights)
    softmax_b_kernel<<<(LDIM * LDIM) / 256, 256>>>();
    // GEMM2: out tiles
    gemm2_kernel<<<dim3(LDIM / 128, CDIM / 128, BATCH), 128, smem2>>>(out);
}